// round 4
// baseline (speedup 1.0000x reference)
#include <cuda_runtime.h>
#include <cuda_bf16.h>
#include <math.h>
#include <stdint.h>

// ---------------- Problem constants ----------------
#define BATCH   4
#define SEQ     2048
#define ROWS    (BATCH*SEQ)      // 8192
#define DIMS    1024
#define STATE   2048             // 2*DIMS
#define NTOT    (4*STATE)        // 8192 interleaved cols (K,u,gin,gout per state)
#define TCH     128              // scan chunk length
#define NCH     (SEQ/TCH)        // 16 chunks

// ---------------- Scratch (device globals; no allocation allowed) ----------------
__device__ __nv_bfloat16 g_xn[(size_t)ROWS*DIMS];       // 16MB  normalized input (bf16)
__device__ __nv_bfloat16 g_WT[(size_t)NTOT*DIMS];       // 16MB  interleaved [Wk|Wugg]^T bf16
__device__ __nv_bfloat16 g_WoutT[(size_t)DIMS*STATE];   // 4MB   Wout^T as [n,k] bf16
__device__ float g_A[(size_t)ROWS*STATE];               // 64MB  a   = sig(K)
__device__ float g_U[(size_t)ROWS*STATE];               // 64MB  u'  = u*sig(gin)*(1-a)
__device__ float g_G[(size_t)ROWS*STATE];               // 64MB  g   = sig(gout)
__device__ __nv_bfloat16 g_out1[(size_t)ROWS*STATE];    // 32MB  h*g bf16
__device__ float g_chA[BATCH*NCH*STATE];
__device__ float g_chB[BATCH*NCH*STATE];
__device__ float g_hin[BATCH*NCH*STATE];

// ---------------- Helpers ----------------
__device__ __forceinline__ uint32_t smem_u32(const void* p) {
    uint32_t a;
    asm("{ .reg .u64 t; cvta.to.shared.u64 t, %1; cvt.u32.u64 %0, t; }" : "=r"(a) : "l"(p));
    return a;
}
__device__ __forceinline__ void cp16(uint32_t dst, const void* src) {
    asm volatile("cp.async.cg.shared.global [%0], [%1], 16;" :: "r"(dst), "l"(src) : "memory");
}
#define CP_COMMIT() asm volatile("cp.async.commit_group;" ::: "memory")

__device__ __forceinline__ void ldm_x4(uint32_t* r, uint32_t addr) {
    asm volatile("ldmatrix.sync.aligned.m8n8.x4.shared.b16 {%0,%1,%2,%3}, [%4];"
                 : "=r"(r[0]), "=r"(r[1]), "=r"(r[2]), "=r"(r[3]) : "r"(addr));
}
__device__ __forceinline__ void mma_bf16(float* c, const uint32_t* a,
                                         uint32_t b0, uint32_t b1) {
    asm volatile(
        "mma.sync.aligned.m16n8k16.row.col.f32.bf16.bf16.f32 "
        "{%0,%1,%2,%3},{%4,%5,%6,%7},{%8,%9},{%0,%1,%2,%3};"
        : "+f"(c[0]), "+f"(c[1]), "+f"(c[2]), "+f"(c[3])
        : "r"(a[0]), "r"(a[1]), "r"(a[2]), "r"(a[3]), "r"(b0), "r"(b1));
}
__device__ __forceinline__ float sigm(float v) { return 1.0f / (1.0f + expf(-v)); }

// ---------------- RMS split norm -> bf16 ----------------
__global__ void rmsnorm_kernel(const float* __restrict__ x,
                               const float* __restrict__ ls,
                               const float* __restrict__ rs,
                               const float* __restrict__ ss,
                               __nv_bfloat16* __restrict__ xn) {
    __shared__ float wsum[8];
    int row = blockIdx.x;
    int tid = threadIdx.x;                 // 256 threads, 4 elems each
    const float* xr = x + (size_t)row * DIMS;
    float4 xv = ((const float4*)xr)[tid];
    float s = xv.x*xv.x + xv.y*xv.y + xv.z*xv.z + xv.w*xv.w;
    #pragma unroll
    for (int o = 16; o; o >>= 1) s += __shfl_xor_sync(0xffffffffu, s, o);
    if ((tid & 31) == 0) wsum[tid >> 5] = s;
    __syncthreads();
    int half = tid >> 7;
    float tot = wsum[half*4+0] + wsum[half*4+1] + wsum[half*4+2] + wsum[half*4+3];
    float n = sqrtf(tot) * 0.04419417382415922f + 1e-8f;   // 1/sqrt(512)
    float inv = 1.0f / n;
    const float* sc = half ? rs : ls;
    int jb = (tid*4) & 511;
    float4 scv = ((const float4*)sc)[jb >> 2];
    float4 ssv = ((const float4*)ss)[tid];
    __nv_bfloat162 p0 = __floats2bfloat162_rn(xv.x * scv.x * inv * ssv.x,
                                              xv.y * scv.y * inv * ssv.y);
    __nv_bfloat162 p1 = __floats2bfloat162_rn(xv.z * scv.z * inv * ssv.z,
                                              xv.w * scv.w * inv * ssv.w);
    __nv_bfloat162* dst = (__nv_bfloat162*)(xn + (size_t)row * DIMS);
    dst[tid*2]   = p0;
    dst[tid*2+1] = p1;
}

// ---------------- Plain transpose fp32 -> bf16: dst[c*R + r] = src[r*C + c] ----------------
__global__ void transpose_bf16(const float* __restrict__ src, __nv_bfloat16* __restrict__ dst,
                               int R, int C) {
    __shared__ float tile[32][33];
    int r0 = blockIdx.y * 32, c0 = blockIdx.x * 32;
    int tx = threadIdx.x, ty = threadIdx.y;   // 32 x 8
    #pragma unroll
    for (int i = 0; i < 32; i += 8)
        tile[ty+i][tx] = src[(size_t)(r0+ty+i)*C + c0 + tx];
    __syncthreads();
    #pragma unroll
    for (int i = 0; i < 32; i += 8)
        dst[(size_t)(c0+ty+i)*R + r0 + tx] = __float2bfloat16_rn(tile[tx][ty+i]);
}

// ---------------- Interleaving transpose: dst[(4c+off)*1024 + k] = src[k*srcLD + c] ----------------
// src has 1024 rows; c ranges over 2048 columns of the given view.
__global__ void transpose_pack(const float* __restrict__ src, int srcLD,
                               __nv_bfloat16* __restrict__ dst, int off) {
    __shared__ float tile[32][33];
    int r0 = blockIdx.y * 32, c0 = blockIdx.x * 32;
    int tx = threadIdx.x, ty = threadIdx.y;   // 32 x 8
    #pragma unroll
    for (int i = 0; i < 32; i += 8)
        tile[ty+i][tx] = src[(size_t)(r0+ty+i)*srcLD + c0 + tx];
    __syncthreads();
    #pragma unroll
    for (int i = 0; i < 32; i += 8)
        dst[(size_t)(4*(c0+ty+i)+off)*1024 + r0 + tx] = __float2bfloat16_rn(tile[tx][ty+i]);
}

// ---------------- Legacy-MMA bf16 GEMM: 128x256 CTA tile, warp 64x64 ----------------
// BK=64, 3-stage cp.async pipeline, 256 threads (8 warps 2x4), 1 CTA/SM.
// mode 0: fused GatedSSM epilogue -> planes A/U/G (interleaved weight layout)
// mode 1: y = acc + resid
#define BK 64
#define NST 3
#define AST (128*BK*2)         // 16384 B per A stage
#define BST (256*BK*2)         // 32768 B per B stage
#define GEMM_SMEM (NST*(AST+BST))   // 147456 B

__device__ __forceinline__ void fill_tiles(uint32_t aS, uint32_t bS,
        const __nv_bfloat16* __restrict__ A, const __nv_bfloat16* __restrict__ B,
        int m0, int n0, int K, int k0, int tid) {
    #pragma unroll
    for (int i = 0; i < 4; i++) {              // A: 128 rows x 8 16B-chunks
        int idx = tid + i*256;
        int r = idx >> 3, c = idx & 7;
        cp16(aS + r*128 + ((c ^ (r & 7)) << 4),
             A + (size_t)(m0 + r)*K + k0 + c*8);
    }
    #pragma unroll
    for (int i = 0; i < 8; i++) {              // B: 256 rows x 8 16B-chunks
        int idx = tid + i*256;
        int r = idx >> 3, c = idx & 7;
        cp16(bS + r*128 + ((c ^ (r & 7)) << 4),
             B + (size_t)(n0 + r)*K + k0 + c*8);
    }
    CP_COMMIT();
}

__global__ void __launch_bounds__(256, 1)
gemm_bf16(const __nv_bfloat16* __restrict__ A, const __nv_bfloat16* __restrict__ B,
          int N, int K, int NIT, int mode,
          float* __restrict__ pA, float* __restrict__ pU, float* __restrict__ pG,
          float* __restrict__ Cout, const float* __restrict__ resid) {
    extern __shared__ char smraw[];
    const uint32_t sbase = smem_u32(smraw);

    const int tid  = threadIdx.x;
    const int wid  = tid >> 5;
    const int lane = tid & 31;
    const int m0 = blockIdx.y * 128;
    const int n0 = blockIdx.x * 256;
    const int wm0 = (wid >> 2) * 64;      // warp row origin (0/64)
    const int wn0 = (wid & 3) * 64;       // warp col origin (0/64/128/192)
    const int blk = lane >> 3;            // 0..3
    const int lr8 = lane & 7;
    const int kb2 = (blk >> 1) * 16;      // +16B for k8..15 half

    uint32_t offA[4], xrA[4], offB[4], xrB[4];
    #pragma unroll
    for (int mt = 0; mt < 4; mt++) {
        int r = wm0 + mt*16 + (blk & 1)*8 + lr8;
        offA[mt] = (uint32_t)r * 128u;
        xrA[mt]  = (uint32_t)(r & 7) << 4;
    }
    #pragma unroll
    for (int np = 0; np < 4; np++) {
        int r = wn0 + np*16 + (blk & 1)*8 + lr8;
        offB[np] = (uint32_t)r * 128u;
        xrB[np]  = (uint32_t)(r & 7) << 4;
    }

    float c[4][8][4];
    #pragma unroll
    for (int i = 0; i < 4; i++)
        #pragma unroll
        for (int j = 0; j < 8; j++)
            #pragma unroll
            for (int e = 0; e < 4; e++) c[i][j][e] = 0.0f;

    #pragma unroll
    for (int pf = 0; pf < NST; ++pf)
        fill_tiles(sbase + pf*(AST+BST), sbase + pf*(AST+BST) + AST,
                   A, B, m0, n0, K, pf*BK, tid);

    for (int it = 0; it < NIT; ++it) {
        const int s = it % NST;
        const uint32_t aS = sbase + s*(AST+BST);
        const uint32_t bS = aS + AST;

        int rem = NIT - 1 - it;
        if (rem >= 2)      asm volatile("cp.async.wait_group 2;" ::: "memory");
        else if (rem == 1) asm volatile("cp.async.wait_group 1;" ::: "memory");
        else               asm volatile("cp.async.wait_group 0;" ::: "memory");
        __syncthreads();

        #pragma unroll
        for (int kk = 0; kk < 4; ++kk) {
            uint32_t a[4][4], b[4][4];
            const uint32_t kbase = (uint32_t)(kk*32) + kb2;
            #pragma unroll
            for (int mt = 0; mt < 4; mt++)
                ldm_x4(a[mt], aS + offA[mt] + (kbase ^ xrA[mt]));
            #pragma unroll
            for (int np = 0; np < 4; np++)
                ldm_x4(b[np], bS + offB[np] + (kbase ^ xrB[np]));
            #pragma unroll
            for (int mt = 0; mt < 4; mt++)
                #pragma unroll
                for (int nt = 0; nt < 8; nt++) {
                    int np = nt >> 1, odd = nt & 1;
                    mma_bf16(c[mt][nt], a[mt], b[np][odd], b[np][2 + odd]);
                }
        }
        __syncthreads();

        if (it + NST < NIT)
            fill_tiles(aS, bS, A, B, m0, n0, K, (it + NST)*BK, tid);
    }

    const int g = lane >> 2, tig = lane & 3;
    if (mode == 0) {
        // Interleaved cols (K,u,gin,gout). Even tig holds (K,u), odd holds (gin,gout).
        #pragma unroll
        for (int mt = 0; mt < 4; mt++) {
            int row = m0 + wm0 + mt*16 + g;
            #pragma unroll
            for (int nt = 0; nt < 8; nt++) {
                int col = n0 + wn0 + nt*8 + 2*tig;
                float v0 = c[mt][nt][0], v1 = c[mt][nt][1];
                float v2 = c[mt][nt][2], v3 = c[mt][nt][3];
                float o0 = __shfl_xor_sync(0xffffffffu, v0, 1);
                float o1 = __shfl_xor_sync(0xffffffffu, v1, 1);
                float o2 = __shfl_xor_sync(0xffffffffu, v2, 1);
                float o3 = __shfl_xor_sync(0xffffffffu, v3, 1);
                if ((lane & 1) == 0) {
                    int st = col >> 2;
                    float aa0 = sigm(v0);
                    float up0 = v1 * sigm(o0) * (1.0f - aa0);
                    float gg0 = sigm(o1);
                    size_t p0i = (size_t)row * STATE + st;
                    pA[p0i] = aa0; pU[p0i] = up0; pG[p0i] = gg0;
                    float aa1 = sigm(v2);
                    float up1 = v3 * sigm(o2) * (1.0f - aa1);
                    float gg1 = sigm(o3);
                    size_t p1i = (size_t)(row + 8) * STATE + st;
                    pA[p1i] = aa1; pU[p1i] = up1; pG[p1i] = gg1;
                }
            }
        }
    } else {
        #pragma unroll
        for (int mt = 0; mt < 4; mt++) {
            int row = m0 + wm0 + mt*16 + g;
            #pragma unroll
            for (int nt = 0; nt < 8; nt++) {
                int col = n0 + wn0 + nt*8 + 2*tig;
                float v0 = c[mt][nt][0] + resid[(size_t)row * N + col];
                float v1 = c[mt][nt][1] + resid[(size_t)row * N + col + 1];
                float v2 = c[mt][nt][2] + resid[(size_t)(row+8) * N + col];
                float v3 = c[mt][nt][3] + resid[(size_t)(row+8) * N + col + 1];
                *(float2*)(Cout + (size_t)row * N + col)     = make_float2(v0, v1);
                *(float2*)(Cout + (size_t)(row+8) * N + col) = make_float2(v2, v3);
            }
        }
    }
}

// ---------------- Chunked linear-recurrence scan over planes ----------------
__global__ void scan_phase1(const float* __restrict__ Ap, const float* __restrict__ Up,
                            float* __restrict__ chA, float* __restrict__ chB) {
    int cidx  = blockIdx.x * blockDim.x + threadIdx.x;   // 0..2047
    int chunk = blockIdx.y;
    int b     = blockIdx.z;
    float Aacc = 1.0f, Bacc = 0.0f;
    int t0 = chunk * TCH;
    for (int tl = 0; tl < TCH; tl++) {
        int t = t0 + tl;
        size_t row = (size_t)b * SEQ + t;
        float a  = (t == 0) ? 1.0f : Ap[(row - 1) * STATE + cidx];
        float up = Up[row * STATE + cidx];
        Aacc = a * Aacc;
        Bacc = a * Bacc + up;
    }
    int idx = (b * NCH + chunk) * STATE + cidx;
    chA[idx] = Aacc;
    chB[idx] = Bacc;
}

__global__ void scan_phase2(const float* __restrict__ chA,
                            const float* __restrict__ chB,
                            float* __restrict__ hin) {
    int i = blockIdx.x * blockDim.x + threadIdx.x;   // b*2048+c
    int b = i >> 11, cidx = i & 2047;
    float h = 0.0f;
    for (int ch = 0; ch < NCH; ch++) {
        int idx = (b * NCH + ch) * STATE + cidx;
        hin[idx] = h;
        h = chA[idx] * h + chB[idx];
    }
}

__global__ void scan_phase3(const float* __restrict__ Ap, const float* __restrict__ Up,
                            const float* __restrict__ Gp,
                            const float* __restrict__ hin,
                            __nv_bfloat16* __restrict__ out1) {
    int cidx  = blockIdx.x * blockDim.x + threadIdx.x;
    int chunk = blockIdx.y;
    int b     = blockIdx.z;
    float h = hin[(b * NCH + chunk) * STATE + cidx];
    int t0 = chunk * TCH;
    for (int tl = 0; tl < TCH; tl++) {
        int t = t0 + tl;
        size_t row = (size_t)b * SEQ + t;
        float a  = (t == 0) ? 1.0f : Ap[(row - 1) * STATE + cidx];
        float up = Up[row * STATE + cidx];
        h = a * h + up;
        out1[row * STATE + cidx] = __float2bfloat16_rn(h * Gp[row * STATE + cidx]);
    }
}

// ---------------- Launch ----------------
extern "C" void kernel_launch(void* const* d_in, const int* in_sizes, int n_in,
                              void* d_out, int out_size) {
    const float* x    = (const float*)d_in[0];
    const float* ls   = (const float*)d_in[1];
    const float* rs   = (const float*)d_in[2];
    const float* ss   = (const float*)d_in[3];
    const float* Wk   = (const float*)d_in[4];
    const float* Wugg = (const float*)d_in[5];
    const float* Wout = (const float*)d_in[6];
    float* y = (float*)d_out;

    __nv_bfloat16 *p_xn, *p_WT, *p_WoutT, *p_out1;
    float *p_A, *p_U, *p_G, *p_chA, *p_chB, *p_hin;
    cudaGetSymbolAddress((void**)&p_xn,    g_xn);
    cudaGetSymbolAddress((void**)&p_WT,    g_WT);
    cudaGetSymbolAddress((void**)&p_WoutT, g_WoutT);
    cudaGetSymbolAddress((void**)&p_A,     g_A);
    cudaGetSymbolAddress((void**)&p_U,     g_U);
    cudaGetSymbolAddress((void**)&p_G,     g_G);
    cudaGetSymbolAddress((void**)&p_out1,  g_out1);
    cudaGetSymbolAddress((void**)&p_chA,   g_chA);
    cudaGetSymbolAddress((void**)&p_chB,   g_chB);
    cudaGetSymbolAddress((void**)&p_hin,   g_hin);

    cudaFuncSetAttribute(gemm_bf16, cudaFuncAttributeMaxDynamicSharedMemorySize, GEMM_SMEM);

    // 1) RMS split norm -> bf16
    rmsnorm_kernel<<<ROWS, 256>>>(x, ls, rs, ss, p_xn);

    // 2) Weights: interleaved [K,u,gin,gout] per state + plain Wout^T
    {
        dim3 blk(32, 8);
        dim3 grd(2048/32, 1024/32);
        transpose_pack<<<grd, blk>>>(Wk,          2048, p_WT, 0);
        transpose_pack<<<grd, blk>>>(Wugg,        6144, p_WT, 1);
        transpose_pack<<<grd, blk>>>(Wugg + 2048, 6144, p_WT, 2);
        transpose_pack<<<grd, blk>>>(Wugg + 4096, 6144, p_WT, 3);
        transpose_bf16<<<dim3(1024/32, 2048/32), blk>>>(Wout, p_WoutT, 2048, 1024);
    }

    // 3) GEMM1 + fused gate epilogue -> planes A/U/G
    gemm_bf16<<<dim3(NTOT/256, ROWS/128), 256, GEMM_SMEM>>>(
        p_xn, p_WT, NTOT, DIMS, DIMS/BK, 0, p_A, p_U, p_G, nullptr, nullptr);

    // 4) Scan
    scan_phase1<<<dim3(STATE/256, NCH, BATCH), 256>>>(p_A, p_U, p_chA, p_chB);
    scan_phase2<<<(BATCH*STATE)/256, 256>>>(p_chA, p_chB, p_hin);
    scan_phase3<<<dim3(STATE/256, NCH, BATCH), 256>>>(p_A, p_U, p_G, p_hin, p_out1);

    // 5) GEMM2: y = out1 @ Wout + x
    gemm_bf16<<<dim3(DIMS/256, ROWS/128), 256, GEMM_SMEM>>>(
        p_out1, p_WoutT, DIMS, STATE, STATE/BK, 1, nullptr, nullptr, nullptr, y, x);
}

// round 5
// speedup vs baseline: 1.1771x; 1.1771x over previous
#include <cuda_runtime.h>
#include <cuda_bf16.h>
#include <math.h>
#include <stdint.h>

// ---------------- Problem constants ----------------
#define BATCH   4
#define SEQ     2048
#define ROWS    (BATCH*SEQ)      // 8192
#define DIMS    1024
#define STATE   2048             // 2*DIMS
#define NTOT    (4*STATE)        // 8192 interleaved cols (K,u,gin,gout per state)
#define TCH     128              // scan chunk length
#define NCH     (SEQ/TCH)        // 16 chunks

// ---------------- Scratch (device globals; no allocation allowed) ----------------
__device__ __nv_bfloat16 g_xn[(size_t)ROWS*DIMS];       // 16MB  normalized input (bf16)
__device__ __nv_bfloat16 g_WT[(size_t)NTOT*DIMS];       // 16MB  interleaved [Wk|Wugg]^T bf16
__device__ __nv_bfloat16 g_WoutT[(size_t)DIMS*STATE];   // 4MB   Wout^T as [n,k] bf16
__device__ float g_A[(size_t)ROWS*STATE];               // 64MB  a   = sig(K)
__device__ float g_U[(size_t)ROWS*STATE];               // 64MB  u'  = u*sig(gin)*(1-a)
__device__ float g_G[(size_t)ROWS*STATE];               // 64MB  g   = sig(gout)
__device__ __nv_bfloat16 g_out1[(size_t)ROWS*STATE];    // 32MB  h*g bf16
__device__ float g_chA[BATCH*NCH*STATE];
__device__ float g_chB[BATCH*NCH*STATE];
__device__ float g_hin[BATCH*NCH*STATE];

// ---------------- Helpers ----------------
__device__ __forceinline__ uint32_t smem_u32(const void* p) {
    uint32_t a;
    asm("{ .reg .u64 t; cvta.to.shared.u64 t, %1; cvt.u32.u64 %0, t; }" : "=r"(a) : "l"(p));
    return a;
}
__device__ __forceinline__ void cp16(uint32_t dst, const void* src) {
    asm volatile("cp.async.cg.shared.global [%0], [%1], 16;" :: "r"(dst), "l"(src) : "memory");
}
#define CP_COMMIT() asm volatile("cp.async.commit_group;" ::: "memory")

__device__ __forceinline__ void ldm_x4(uint32_t* r, uint32_t addr) {
    asm volatile("ldmatrix.sync.aligned.m8n8.x4.shared.b16 {%0,%1,%2,%3}, [%4];"
                 : "=r"(r[0]), "=r"(r[1]), "=r"(r[2]), "=r"(r[3]) : "r"(addr));
}
__device__ __forceinline__ void mma_bf16(float* c, const uint32_t* a,
                                         uint32_t b0, uint32_t b1) {
    asm volatile(
        "mma.sync.aligned.m16n8k16.row.col.f32.bf16.bf16.f32 "
        "{%0,%1,%2,%3},{%4,%5,%6,%7},{%8,%9},{%0,%1,%2,%3};"
        : "+f"(c[0]), "+f"(c[1]), "+f"(c[2]), "+f"(c[3])
        : "r"(a[0]), "r"(a[1]), "r"(a[2]), "r"(a[3]), "r"(b0), "r"(b1));
}
__device__ __forceinline__ float sigm(float v) { return 1.0f / (1.0f + expf(-v)); }

// ---------------- RMS split norm -> bf16 ----------------
__global__ void rmsnorm_kernel(const float* __restrict__ x,
                               const float* __restrict__ ls,
                               const float* __restrict__ rs,
                               const float* __restrict__ ss,
                               __nv_bfloat16* __restrict__ xn) {
    __shared__ float wsum[8];
    int row = blockIdx.x;
    int tid = threadIdx.x;                 // 256 threads, 4 elems each
    const float* xr = x + (size_t)row * DIMS;
    float4 xv = ((const float4*)xr)[tid];
    float s = xv.x*xv.x + xv.y*xv.y + xv.z*xv.z + xv.w*xv.w;
    #pragma unroll
    for (int o = 16; o; o >>= 1) s += __shfl_xor_sync(0xffffffffu, s, o);
    if ((tid & 31) == 0) wsum[tid >> 5] = s;
    __syncthreads();
    int half = tid >> 7;
    float tot = wsum[half*4+0] + wsum[half*4+1] + wsum[half*4+2] + wsum[half*4+3];
    float n = sqrtf(tot) * 0.04419417382415922f + 1e-8f;   // 1/sqrt(512)
    float inv = 1.0f / n;
    const float* sc = half ? rs : ls;
    int jb = (tid*4) & 511;
    float4 scv = ((const float4*)sc)[jb >> 2];
    float4 ssv = ((const float4*)ss)[tid];
    __nv_bfloat162 p0 = __floats2bfloat162_rn(xv.x * scv.x * inv * ssv.x,
                                              xv.y * scv.y * inv * ssv.y);
    __nv_bfloat162 p1 = __floats2bfloat162_rn(xv.z * scv.z * inv * ssv.z,
                                              xv.w * scv.w * inv * ssv.w);
    __nv_bfloat162* dst = (__nv_bfloat162*)(xn + (size_t)row * DIMS);
    dst[tid*2]   = p0;
    dst[tid*2+1] = p1;
}

// ---------------- Plain transpose fp32 -> bf16: dst[c*R + r] = src[r*C + c] ----------------
__global__ void transpose_bf16(const float* __restrict__ src, __nv_bfloat16* __restrict__ dst,
                               int R, int C) {
    __shared__ float tile[32][33];
    int r0 = blockIdx.y * 32, c0 = blockIdx.x * 32;
    int tx = threadIdx.x, ty = threadIdx.y;   // 32 x 8
    #pragma unroll
    for (int i = 0; i < 32; i += 8)
        tile[ty+i][tx] = src[(size_t)(r0+ty+i)*C + c0 + tx];
    __syncthreads();
    #pragma unroll
    for (int i = 0; i < 32; i += 8)
        dst[(size_t)(c0+ty+i)*R + r0 + tx] = __float2bfloat16_rn(tile[tx][ty+i]);
}

// ---------------- Interleaving transpose: dst[(4c+off)*1024 + k] = src[k*srcLD + c] ----------------
__global__ void transpose_pack(const float* __restrict__ src, int srcLD,
                               __nv_bfloat16* __restrict__ dst, int off) {
    __shared__ float tile[32][33];
    int r0 = blockIdx.y * 32, c0 = blockIdx.x * 32;
    int tx = threadIdx.x, ty = threadIdx.y;   // 32 x 8
    #pragma unroll
    for (int i = 0; i < 32; i += 8)
        tile[ty+i][tx] = src[(size_t)(r0+ty+i)*srcLD + c0 + tx];
    __syncthreads();
    #pragma unroll
    for (int i = 0; i < 32; i += 8)
        dst[(size_t)(4*(c0+ty+i)+off)*1024 + r0 + tx] = __float2bfloat16_rn(tile[tx][ty+i]);
}

// ---------------- Legacy-MMA bf16 GEMM: 128x128 CTA tile, warp 64x32, 2 CTA/SM ----------------
// BK=64, 3-stage single-sync cp.async pipeline (fill leads compute by 2).
// mode 0: fused GatedSSM epilogue -> planes A/U/G (interleaved weight layout)
// mode 1: y = acc + resid
#define BK 64
#define NST 3
#define AST (128*BK*2)         // 16384 B per A stage
#define BST (128*BK*2)         // 16384 B per B stage
#define GEMM_SMEM (NST*(AST+BST))   // 98304 = 96KB

__device__ __forceinline__ void fill_tiles(uint32_t aS, uint32_t bS,
        const __nv_bfloat16* __restrict__ A, const __nv_bfloat16* __restrict__ B,
        int m0, int n0, int K, int k0, int tid) {
    #pragma unroll
    for (int i = 0; i < 4; i++) {              // A: 128 rows x 8 16B-chunks
        int idx = tid + i*256;
        int r = idx >> 3, c = idx & 7;
        cp16(aS + r*128 + ((c ^ (r & 7)) << 4),
             A + (size_t)(m0 + r)*K + k0 + c*8);
    }
    #pragma unroll
    for (int i = 0; i < 4; i++) {              // B: 128 rows x 8 16B-chunks
        int idx = tid + i*256;
        int r = idx >> 3, c = idx & 7;
        cp16(bS + r*128 + ((c ^ (r & 7)) << 4),
             B + (size_t)(n0 + r)*K + k0 + c*8);
    }
    CP_COMMIT();
}

__global__ void __launch_bounds__(256, 2)
gemm_bf16(const __nv_bfloat16* __restrict__ A, const __nv_bfloat16* __restrict__ B,
          int N, int K, int NIT, int mode,
          float* __restrict__ pA, float* __restrict__ pU, float* __restrict__ pG,
          float* __restrict__ Cout, const float* __restrict__ resid) {
    extern __shared__ char smraw[];
    const uint32_t sbase = smem_u32(smraw);

    const int tid  = threadIdx.x;
    const int wid  = tid >> 5;
    const int lane = tid & 31;
    const int m0 = blockIdx.y * 128;
    const int n0 = blockIdx.x * 128;
    const int wm0 = (wid >> 2) * 64;      // warp row origin (0/64)
    const int wn0 = (wid & 3) * 32;       // warp col origin (0/32/64/96)
    const int blk = lane >> 3;            // 0..3
    const int lr8 = lane & 7;
    const int kb2 = (blk >> 1) * 16;      // +16B for k8..15 half

    uint32_t offA[4], xrA[4], offB[2], xrB[2];
    #pragma unroll
    for (int mt = 0; mt < 4; mt++) {
        int r = wm0 + mt*16 + (blk & 1)*8 + lr8;
        offA[mt] = (uint32_t)r * 128u;
        xrA[mt]  = (uint32_t)(r & 7) << 4;
    }
    #pragma unroll
    for (int np = 0; np < 2; np++) {
        int r = wn0 + np*16 + (blk & 1)*8 + lr8;
        offB[np] = (uint32_t)r * 128u;
        xrB[np]  = (uint32_t)(r & 7) << 4;
    }

    float c[4][4][4];
    #pragma unroll
    for (int i = 0; i < 4; i++)
        #pragma unroll
        for (int j = 0; j < 4; j++)
            #pragma unroll
            for (int e = 0; e < 4; e++) c[i][j][e] = 0.0f;

    // Prologue: fill 2 stages (fill leads compute by NST-1)
    fill_tiles(sbase,             sbase + AST,             A, B, m0, n0, K, 0,  tid);
    fill_tiles(sbase + (AST+BST), sbase + (AST+BST) + AST, A, B, m0, n0, K, BK, tid);

    for (int it = 0; it < NIT; ++it) {
        const int s = it % NST;
        const uint32_t aS = sbase + s*(AST+BST);
        const uint32_t bS = aS + AST;

        if (it < NIT - 1) asm volatile("cp.async.wait_group 1;" ::: "memory");
        else              asm volatile("cp.async.wait_group 0;" ::: "memory");
        __syncthreads();   // stage s ready; slot (it+2)%NST free (read finished @ it-1)

        if (it + 2 < NIT) {
            const int f = (it + 2) % NST;
            fill_tiles(sbase + f*(AST+BST), sbase + f*(AST+BST) + AST,
                       A, B, m0, n0, K, (it + 2)*BK, tid);
        }

        #pragma unroll
        for (int kk = 0; kk < 4; ++kk) {
            uint32_t a[4][4], b[2][4];
            const uint32_t kbase = (uint32_t)(kk*32) + kb2;
            #pragma unroll
            for (int mt = 0; mt < 4; mt++)
                ldm_x4(a[mt], aS + offA[mt] + (kbase ^ xrA[mt]));
            #pragma unroll
            for (int np = 0; np < 2; np++)
                ldm_x4(b[np], bS + offB[np] + (kbase ^ xrB[np]));
            #pragma unroll
            for (int mt = 0; mt < 4; mt++)
                #pragma unroll
                for (int nt = 0; nt < 4; nt++) {
                    int np = nt >> 1, odd = nt & 1;
                    mma_bf16(c[mt][nt], a[mt], b[np][odd], b[np][2 + odd]);
                }
        }
    }

    const int g = lane >> 2, tig = lane & 3;
    if (mode == 0) {
        // Interleaved cols (K,u,gin,gout): even-tig lanes hold (K,u), odd hold (gin,gout)
        #pragma unroll
        for (int mt = 0; mt < 4; mt++) {
            int row = m0 + wm0 + mt*16 + g;
            #pragma unroll
            for (int nt = 0; nt < 4; nt++) {
                int col = n0 + wn0 + nt*8 + 2*tig;
                float v0 = c[mt][nt][0], v1 = c[mt][nt][1];
                float v2 = c[mt][nt][2], v3 = c[mt][nt][3];
                float o0 = __shfl_xor_sync(0xffffffffu, v0, 1);
                float o1 = __shfl_xor_sync(0xffffffffu, v1, 1);
                float o2 = __shfl_xor_sync(0xffffffffu, v2, 1);
                float o3 = __shfl_xor_sync(0xffffffffu, v3, 1);
                if ((lane & 1) == 0) {
                    int st = col >> 2;
                    float aa0 = sigm(v0);
                    float up0 = v1 * sigm(o0) * (1.0f - aa0);
                    float gg0 = sigm(o1);
                    size_t p0i = (size_t)row * STATE + st;
                    pA[p0i] = aa0; pU[p0i] = up0; pG[p0i] = gg0;
                    float aa1 = sigm(v2);
                    float up1 = v3 * sigm(o2) * (1.0f - aa1);
                    float gg1 = sigm(o3);
                    size_t p1i = (size_t)(row + 8) * STATE + st;
                    pA[p1i] = aa1; pU[p1i] = up1; pG[p1i] = gg1;
                }
            }
        }
    } else {
        #pragma unroll
        for (int mt = 0; mt < 4; mt++) {
            int row = m0 + wm0 + mt*16 + g;
            #pragma unroll
            for (int nt = 0; nt < 4; nt++) {
                int col = n0 + wn0 + nt*8 + 2*tig;
                float v0 = c[mt][nt][0] + resid[(size_t)row * N + col];
                float v1 = c[mt][nt][1] + resid[(size_t)row * N + col + 1];
                float v2 = c[mt][nt][2] + resid[(size_t)(row+8) * N + col];
                float v3 = c[mt][nt][3] + resid[(size_t)(row+8) * N + col + 1];
                *(float2*)(Cout + (size_t)row * N + col)     = make_float2(v0, v1);
                *(float2*)(Cout + (size_t)(row+8) * N + col) = make_float2(v2, v3);
            }
        }
    }
}

// ---------------- Chunked linear-recurrence scan over planes ----------------
__global__ void scan_phase1(const float* __restrict__ Ap, const float* __restrict__ Up,
                            float* __restrict__ chA, float* __restrict__ chB) {
    int cidx  = blockIdx.x * blockDim.x + threadIdx.x;   // 0..2047
    int chunk = blockIdx.y;
    int b     = blockIdx.z;
    float Aacc = 1.0f, Bacc = 0.0f;
    int t0 = chunk * TCH;
    for (int tl = 0; tl < TCH; tl++) {
        int t = t0 + tl;
        size_t row = (size_t)b * SEQ + t;
        float a  = (t == 0) ? 1.0f : Ap[(row - 1) * STATE + cidx];
        float up = Up[row * STATE + cidx];
        Aacc = a * Aacc;
        Bacc = a * Bacc + up;
    }
    int idx = (b * NCH + chunk) * STATE + cidx;
    chA[idx] = Aacc;
    chB[idx] = Bacc;
}

__global__ void scan_phase2(const float* __restrict__ chA,
                            const float* __restrict__ chB,
                            float* __restrict__ hin) {
    int i = blockIdx.x * blockDim.x + threadIdx.x;   // b*2048+c
    int b = i >> 11, cidx = i & 2047;
    float h = 0.0f;
    for (int ch = 0; ch < NCH; ch++) {
        int idx = (b * NCH + ch) * STATE + cidx;
        hin[idx] = h;
        h = chA[idx] * h + chB[idx];
    }
}

__global__ void scan_phase3(const float* __restrict__ Ap, const float* __restrict__ Up,
                            const float* __restrict__ Gp,
                            const float* __restrict__ hin,
                            __nv_bfloat16* __restrict__ out1) {
    int cidx  = blockIdx.x * blockDim.x + threadIdx.x;
    int chunk = blockIdx.y;
    int b     = blockIdx.z;
    float h = hin[(b * NCH + chunk) * STATE + cidx];
    int t0 = chunk * TCH;
    for (int tl = 0; tl < TCH; tl++) {
        int t = t0 + tl;
        size_t row = (size_t)b * SEQ + t;
        float a  = (t == 0) ? 1.0f : Ap[(row - 1) * STATE + cidx];
        float up = Up[row * STATE + cidx];
        h = a * h + up;
        out1[row * STATE + cidx] = __float2bfloat16_rn(h * Gp[row * STATE + cidx]);
    }
}

// ---------------- Launch ----------------
extern "C" void kernel_launch(void* const* d_in, const int* in_sizes, int n_in,
                              void* d_out, int out_size) {
    const float* x    = (const float*)d_in[0];
    const float* ls   = (const float*)d_in[1];
    const float* rs   = (const float*)d_in[2];
    const float* ss   = (const float*)d_in[3];
    const float* Wk   = (const float*)d_in[4];
    const float* Wugg = (const float*)d_in[5];
    const float* Wout = (const float*)d_in[6];
    float* y = (float*)d_out;

    __nv_bfloat16 *p_xn, *p_WT, *p_WoutT, *p_out1;
    float *p_A, *p_U, *p_G, *p_chA, *p_chB, *p_hin;
    cudaGetSymbolAddress((void**)&p_xn,    g_xn);
    cudaGetSymbolAddress((void**)&p_WT,    g_WT);
    cudaGetSymbolAddress((void**)&p_WoutT, g_WoutT);
    cudaGetSymbolAddress((void**)&p_A,     g_A);
    cudaGetSymbolAddress((void**)&p_U,     g_U);
    cudaGetSymbolAddress((void**)&p_G,     g_G);
    cudaGetSymbolAddress((void**)&p_out1,  g_out1);
    cudaGetSymbolAddress((void**)&p_chA,   g_chA);
    cudaGetSymbolAddress((void**)&p_chB,   g_chB);
    cudaGetSymbolAddress((void**)&p_hin,   g_hin);

    cudaFuncSetAttribute(gemm_bf16, cudaFuncAttributeMaxDynamicSharedMemorySize, GEMM_SMEM);

    // 1) RMS split norm -> bf16
    rmsnorm_kernel<<<ROWS, 256>>>(x, ls, rs, ss, p_xn);

    // 2) Weights: interleaved [K,u,gin,gout] per state + plain Wout^T
    {
        dim3 blk(32, 8);
        dim3 grd(2048/32, 1024/32);
        transpose_pack<<<grd, blk>>>(Wk,          2048, p_WT, 0);
        transpose_pack<<<grd, blk>>>(Wugg,        6144, p_WT, 1);
        transpose_pack<<<grd, blk>>>(Wugg + 2048, 6144, p_WT, 2);
        transpose_pack<<<grd, blk>>>(Wugg + 4096, 6144, p_WT, 3);
        transpose_bf16<<<dim3(1024/32, 2048/32), blk>>>(Wout, p_WoutT, 2048, 1024);
    }

    // 3) GEMM1 + fused gate epilogue -> planes A/U/G
    gemm_bf16<<<dim3(NTOT/128, ROWS/128), 256, GEMM_SMEM>>>(
        p_xn, p_WT, NTOT, DIMS, DIMS/BK, 0, p_A, p_U, p_G, nullptr, nullptr);

    // 4) Scan
    scan_phase1<<<dim3(STATE/256, NCH, BATCH), 256>>>(p_A, p_U, p_chA, p_chB);
    scan_phase2<<<(BATCH*STATE)/256, 256>>>(p_chA, p_chB, p_hin);
    scan_phase3<<<dim3(STATE/256, NCH, BATCH), 256>>>(p_A, p_U, p_G, p_hin, p_out1);

    // 5) GEMM2: y = out1 @ Wout + x
    gemm_bf16<<<dim3(DIMS/128, ROWS/128), 256, GEMM_SMEM>>>(
        p_out1, p_WoutT, DIMS, STATE, STATE/BK, 1, nullptr, nullptr, nullptr, y, x);
}

// round 7
// speedup vs baseline: 1.2165x; 1.0335x over previous
#include <cuda_runtime.h>
#include <cuda_bf16.h>
#include <math.h>
#include <stdint.h>

// ---------------- Problem constants ----------------
#define BATCH   4
#define SEQ     2048
#define ROWS    (BATCH*SEQ)      // 8192
#define DIMS    1024
#define STATE   2048             // 2*DIMS
#define NTOT    (4*STATE)        // 8192 interleaved cols (K,u,gin,gout per state)
#define TCH     128              // scan chunk length
#define NCH     (SEQ/TCH)        // 16 chunks

// ---------------- Scratch (device globals; no allocation allowed) ----------------
__device__ __nv_bfloat16 g_xn[(size_t)ROWS*DIMS];       // 16MB  normalized input (bf16)
__device__ __nv_bfloat16 g_WT[(size_t)NTOT*DIMS];       // 16MB  interleaved [Wk|Wugg]^T bf16
__device__ __nv_bfloat16 g_WoutT[(size_t)DIMS*STATE];   // 4MB   Wout^T as [n,k] bf16
__device__ float         g_A[(size_t)ROWS*STATE];       // 64MB  a  = sig(K)   fp32 (recurrence-critical)
__device__ __nv_bfloat16 g_U[(size_t)ROWS*STATE];       // 32MB  u' = u sig(gin)(1-a) bf16
__device__ __nv_bfloat16 g_G[(size_t)ROWS*STATE];       // 32MB  g  = sig(gout) bf16
__device__ __nv_bfloat16 g_out1[(size_t)ROWS*STATE];    // 32MB  h*g bf16
__device__ float g_chA[BATCH*NCH*STATE];
__device__ float g_chB[BATCH*NCH*STATE];
__device__ float g_hin[BATCH*NCH*STATE];

// ---------------- Helpers ----------------
__device__ __forceinline__ uint32_t smem_u32(const void* p) {
    uint32_t a;
    asm("{ .reg .u64 t; cvta.to.shared.u64 t, %1; cvt.u32.u64 %0, t; }" : "=r"(a) : "l"(p));
    return a;
}
__device__ __forceinline__ void cp16(uint32_t dst, const void* src) {
    asm volatile("cp.async.cg.shared.global [%0], [%1], 16;" :: "r"(dst), "l"(src) : "memory");
}
#define CP_COMMIT() asm volatile("cp.async.commit_group;" ::: "memory")

__device__ __forceinline__ void ldm_x4(uint32_t* r, uint32_t addr) {
    asm volatile("ldmatrix.sync.aligned.m8n8.x4.shared.b16 {%0,%1,%2,%3}, [%4];"
                 : "=r"(r[0]), "=r"(r[1]), "=r"(r[2]), "=r"(r[3]) : "r"(addr));
}
__device__ __forceinline__ void mma_bf16(float* c, const uint32_t* a,
                                         uint32_t b0, uint32_t b1) {
    asm volatile(
        "mma.sync.aligned.m16n8k16.row.col.f32.bf16.bf16.f32 "
        "{%0,%1,%2,%3},{%4,%5,%6,%7},{%8,%9},{%0,%1,%2,%3};"
        : "+f"(c[0]), "+f"(c[1]), "+f"(c[2]), "+f"(c[3])
        : "r"(a[0]), "r"(a[1]), "r"(a[2]), "r"(a[3]), "r"(b0), "r"(b1));
}
__device__ __forceinline__ float sigm(float v) { return 1.0f / (1.0f + expf(-v)); }

// ---------------- RMS split norm -> bf16 ----------------
__global__ void rmsnorm_kernel(const float* __restrict__ x,
                               const float* __restrict__ ls,
                               const float* __restrict__ rs,
                               const float* __restrict__ ss,
                               __nv_bfloat16* __restrict__ xn) {
    __shared__ float wsum[8];
    int row = blockIdx.x;
    int tid = threadIdx.x;                 // 256 threads, 4 elems each
    const float* xr = x + (size_t)row * DIMS;
    float4 xv = ((const float4*)xr)[tid];
    float s = xv.x*xv.x + xv.y*xv.y + xv.z*xv.z + xv.w*xv.w;
    #pragma unroll
    for (int o = 16; o; o >>= 1) s += __shfl_xor_sync(0xffffffffu, s, o);
    if ((tid & 31) == 0) wsum[tid >> 5] = s;
    __syncthreads();
    int half = tid >> 7;
    float tot = wsum[half*4+0] + wsum[half*4+1] + wsum[half*4+2] + wsum[half*4+3];
    float n = sqrtf(tot) * 0.04419417382415922f + 1e-8f;   // 1/sqrt(512)
    float inv = 1.0f / n;
    const float* sc = half ? rs : ls;
    int jb = (tid*4) & 511;
    float4 scv = ((const float4*)sc)[jb >> 2];
    float4 ssv = ((const float4*)ss)[tid];
    __nv_bfloat162 p0 = __floats2bfloat162_rn(xv.x * scv.x * inv * ssv.x,
                                              xv.y * scv.y * inv * ssv.y);
    __nv_bfloat162 p1 = __floats2bfloat162_rn(xv.z * scv.z * inv * ssv.z,
                                              xv.w * scv.w * inv * ssv.w);
    __nv_bfloat162* dst = (__nv_bfloat162*)(xn + (size_t)row * DIMS);
    dst[tid*2]   = p0;
    dst[tid*2+1] = p1;
}

// ---------------- Plain transpose fp32 -> bf16 ----------------
__global__ void transpose_bf16(const float* __restrict__ src, __nv_bfloat16* __restrict__ dst,
                               int R, int C) {
    __shared__ float tile[32][33];
    int r0 = blockIdx.y * 32, c0 = blockIdx.x * 32;
    int tx = threadIdx.x, ty = threadIdx.y;   // 32 x 8
    #pragma unroll
    for (int i = 0; i < 32; i += 8)
        tile[ty+i][tx] = src[(size_t)(r0+ty+i)*C + c0 + tx];
    __syncthreads();
    #pragma unroll
    for (int i = 0; i < 32; i += 8)
        dst[(size_t)(c0+ty+i)*R + r0 + tx] = __float2bfloat16_rn(tile[tx][ty+i]);
}

// ---------------- Interleaving transpose: dst[(4c+off)*1024 + k] = src[k*srcLD + c] ----------------
__global__ void transpose_pack(const float* __restrict__ src, int srcLD,
                               __nv_bfloat16* __restrict__ dst, int off) {
    __shared__ float tile[32][33];
    int r0 = blockIdx.y * 32, c0 = blockIdx.x * 32;
    int tx = threadIdx.x, ty = threadIdx.y;   // 32 x 8
    #pragma unroll
    for (int i = 0; i < 32; i += 8)
        tile[ty+i][tx] = src[(size_t)(r0+ty+i)*srcLD + c0 + tx];
    __syncthreads();
    #pragma unroll
    for (int i = 0; i < 32; i += 8)
        dst[(size_t)(4*(c0+ty+i)+off)*1024 + r0 + tx] = __float2bfloat16_rn(tile[tx][ty+i]);
}

// ---------------- Legacy-MMA bf16 GEMM: 128x128 CTA tile, warp 64x32, 2 CTA/SM ----------------
// Mainloop identical to the 631us R3 kernel (double-sync, 3-stage, fill leads by 3).
// mode 0: fused GatedSSM epilogue -> A fp32, U/G bf16 planes via smem staging
// mode 1: y = acc + resid (fp32 out)
#define BK 64
#define NST 3
#define AST (128*BK*2)         // 16384 B per A stage
#define BST (128*BK*2)         // 16384 B per B stage
#define GEMM_SMEM (NST*(AST+BST))   // 98304 = 96KB
#define EPA 36                 // A-plane smem pitch in floats (144B, 16B-aligned)
#define EPH 48                 // U/G-plane smem pitch in bf16  (96B, 16B-aligned)

__device__ __forceinline__ void fill_tiles(uint32_t aS, uint32_t bS,
        const __nv_bfloat16* __restrict__ A, const __nv_bfloat16* __restrict__ B,
        int m0, int n0, int K, int k0, int tid) {
    #pragma unroll
    for (int i = 0; i < 4; i++) {              // A: 128 rows x 8 16B-chunks
        int idx = tid + i*256;
        int r = idx >> 3, c = idx & 7;
        cp16(aS + r*128 + ((c ^ (r & 7)) << 4),
             A + (size_t)(m0 + r)*K + k0 + c*8);
    }
    #pragma unroll
    for (int i = 0; i < 4; i++) {              // B: 128 rows x 8 16B-chunks
        int idx = tid + i*256;
        int r = idx >> 3, c = idx & 7;
        cp16(bS + r*128 + ((c ^ (r & 7)) << 4),
             B + (size_t)(n0 + r)*K + k0 + c*8);
    }
    CP_COMMIT();
}

__global__ void __launch_bounds__(256, 2)
gemm_bf16(const __nv_bfloat16* __restrict__ A, const __nv_bfloat16* __restrict__ B,
          int N, int K, int NIT, int mode,
          float* __restrict__ pA, __nv_bfloat16* __restrict__ pU,
          __nv_bfloat16* __restrict__ pG,
          float* __restrict__ Cout, const float* __restrict__ resid) {
    extern __shared__ char smraw[];
    const uint32_t sbase = smem_u32(smraw);

    const int tid  = threadIdx.x;
    const int wid  = tid >> 5;
    const int lane = tid & 31;
    const int m0 = blockIdx.y * 128;
    const int n0 = blockIdx.x * 128;
    const int wm0 = (wid >> 2) * 64;      // warp row origin (0/64)
    const int wn0 = (wid & 3) * 32;       // warp col origin (0/32/64/96)
    const int blk = lane >> 3;            // 0..3
    const int lr8 = lane & 7;
    const int kb2 = (blk >> 1) * 16;      // +16B for k8..15 half

    uint32_t offA[4], xrA[4], offB[2], xrB[2];
    #pragma unroll
    for (int mt = 0; mt < 4; mt++) {
        int r = wm0 + mt*16 + (blk & 1)*8 + lr8;
        offA[mt] = (uint32_t)r * 128u;
        xrA[mt]  = (uint32_t)(r & 7) << 4;
    }
    #pragma unroll
    for (int np = 0; np < 2; np++) {
        int r = wn0 + np*16 + (blk & 1)*8 + lr8;
        offB[np] = (uint32_t)r * 128u;
        xrB[np]  = (uint32_t)(r & 7) << 4;
    }

    float c[4][4][4];
    #pragma unroll
    for (int i = 0; i < 4; i++)
        #pragma unroll
        for (int j = 0; j < 4; j++)
            #pragma unroll
            for (int e = 0; e < 4; e++) c[i][j][e] = 0.0f;

    // Prologue: fill all 3 stages (R3 schedule)
    #pragma unroll
    for (int pf = 0; pf < NST; ++pf)
        fill_tiles(sbase + pf*(AST+BST), sbase + pf*(AST+BST) + AST,
                   A, B, m0, n0, K, pf*BK, tid);

    for (int it = 0; it < NIT; ++it) {
        const int s = it % NST;
        const uint32_t aS = sbase + s*(AST+BST);
        const uint32_t bS = aS + AST;

        int rem = NIT - 1 - it;
        if (rem >= 2)      asm volatile("cp.async.wait_group 2;" ::: "memory");
        else if (rem == 1) asm volatile("cp.async.wait_group 1;" ::: "memory");
        else               asm volatile("cp.async.wait_group 0;" ::: "memory");
        __syncthreads();

        #pragma unroll
        for (int kk = 0; kk < 4; ++kk) {
            uint32_t a[4][4], b[2][4];
            const uint32_t kbase = (uint32_t)(kk*32) + kb2;
            #pragma unroll
            for (int mt = 0; mt < 4; mt++)
                ldm_x4(a[mt], aS + offA[mt] + (kbase ^ xrA[mt]));
            #pragma unroll
            for (int np = 0; np < 2; np++)
                ldm_x4(b[np], bS + offB[np] + (kbase ^ xrB[np]));
            #pragma unroll
            for (int mt = 0; mt < 4; mt++)
                #pragma unroll
                for (int nt = 0; nt < 4; nt++) {
                    int np = nt >> 1, odd = nt & 1;
                    mma_bf16(c[mt][nt], a[mt], b[np][odd], b[np][2 + odd]);
                }
        }
        __syncthreads();   // everyone done reading stage s

        if (it + 3 < NIT)
            fill_tiles(aS, bS, A, B, m0, n0, K, (it + 3)*BK, tid);
    }

    const int g = lane >> 2, tig = lane & 3;
    if (mode == 0) {
        // Interleaved cols (K,u,gin,gout). Lane^1 pairs (K,u)<->(gin,gout).
        asm volatile("cp.async.wait_group 0;" ::: "memory");
        __syncthreads();   // pipeline smem now reusable
        float* sPA = (float*)smraw;                                    // 128 x EPA f32
        __nv_bfloat16* sPU = (__nv_bfloat16*)(smraw + 128*EPA*4);      // 128 x EPH bf16
        __nv_bfloat16* sPG = sPU + 128*EPH;                            // 128 x EPH bf16
        #pragma unroll
        for (int mt = 0; mt < 4; mt++) {
            int rloc = wm0 + mt*16 + g;
            #pragma unroll
            for (int nt = 0; nt < 4; nt++) {
                float v0 = c[mt][nt][0], v1 = c[mt][nt][1];
                float v2 = c[mt][nt][2], v3 = c[mt][nt][3];
                float o0 = __shfl_xor_sync(0xffffffffu, v0, 1);
                float o1 = __shfl_xor_sync(0xffffffffu, v1, 1);
                float o2 = __shfl_xor_sync(0xffffffffu, v2, 1);
                float o3 = __shfl_xor_sync(0xffffffffu, v3, 1);
                if ((lane & 1) == 0) {
                    int stloc = (wn0 + nt*8 + 2*tig) >> 2;   // 0..31
                    float aa0 = sigm(v0);
                    float up0 = v1 * sigm(o0) * (1.0f - aa0);
                    float gg0 = sigm(o1);
                    float aa1 = sigm(v2);
                    float up1 = v3 * sigm(o2) * (1.0f - aa1);
                    float gg1 = sigm(o3);
                    sPA[rloc*EPA + stloc]       = aa0;
                    sPA[(rloc+8)*EPA + stloc]   = aa1;
                    sPU[rloc*EPH + stloc]       = __float2bfloat16_rn(up0);
                    sPU[(rloc+8)*EPH + stloc]   = __float2bfloat16_rn(up1);
                    sPG[rloc*EPH + stloc]       = __float2bfloat16_rn(gg0);
                    sPG[(rloc+8)*EPH + stloc]   = __float2bfloat16_rn(gg1);
                }
            }
        }
        __syncthreads();
        // copy-out: 128 rows x 32 states. A: 128B/row fp32; U/G: 64B/row bf16.
        {
            int row = tid >> 1, half = tid & 1;
            size_t gb = (size_t)(m0 + row) * STATE + (n0 >> 2) + half*16;
            const float4* sa = (const float4*)(sPA + row*EPA + half*16);
            float4* dA = (float4*)(pA + gb);
            dA[0] = sa[0]; dA[1] = sa[1]; dA[2] = sa[2]; dA[3] = sa[3];
            const float4* su = (const float4*)(sPU + row*EPH + half*16);
            float4* dU = (float4*)(pU + gb);
            dU[0] = su[0]; dU[1] = su[1];
            const float4* sg = (const float4*)(sPG + row*EPH + half*16);
            float4* dG = (float4*)(pG + gb);
            dG[0] = sg[0]; dG[1] = sg[1];
        }
    } else {
        #pragma unroll
        for (int mt = 0; mt < 4; mt++) {
            int row = m0 + wm0 + mt*16 + g;
            #pragma unroll
            for (int nt = 0; nt < 4; nt++) {
                int col = n0 + wn0 + nt*8 + 2*tig;
                float v0 = c[mt][nt][0] + resid[(size_t)row * N + col];
                float v1 = c[mt][nt][1] + resid[(size_t)row * N + col + 1];
                float v2 = c[mt][nt][2] + resid[(size_t)(row+8) * N + col];
                float v3 = c[mt][nt][3] + resid[(size_t)(row+8) * N + col + 1];
                *(float2*)(Cout + (size_t)row * N + col)     = make_float2(v0, v1);
                *(float2*)(Cout + (size_t)(row+8) * N + col) = make_float2(v2, v3);
            }
        }
    }
}

// ---------------- Chunked linear-recurrence scan (A fp32, U/G bf16) ----------------
__global__ void scan_phase1(const float* __restrict__ Ap,
                            const __nv_bfloat16* __restrict__ Up,
                            float* __restrict__ chA, float* __restrict__ chB) {
    int cidx  = blockIdx.x * blockDim.x + threadIdx.x;   // 0..2047
    int chunk = blockIdx.y;
    int b     = blockIdx.z;
    float Aacc = 1.0f, Bacc = 0.0f;
    int t0 = chunk * TCH;
    for (int tl = 0; tl < TCH; tl++) {
        int t = t0 + tl;
        size_t row = (size_t)b * SEQ + t;
        float a  = (t == 0) ? 1.0f : Ap[(row - 1) * STATE + cidx];
        float up = __bfloat162float(Up[row * STATE + cidx]);
        Aacc = a * Aacc;
        Bacc = a * Bacc + up;
    }
    int idx = (b * NCH + chunk) * STATE + cidx;
    chA[idx] = Aacc;
    chB[idx] = Bacc;
}

__global__ void scan_phase2(const float* __restrict__ chA,
                            const float* __restrict__ chB,
                            float* __restrict__ hin) {
    int i = blockIdx.x * blockDim.x + threadIdx.x;   // b*2048+c
    int b = i >> 11, cidx = i & 2047;
    float h = 0.0f;
    for (int ch = 0; ch < NCH; ch++) {
        int idx = (b * NCH + ch) * STATE + cidx;
        hin[idx] = h;
        h = chA[idx] * h + chB[idx];
    }
}

__global__ void scan_phase3(const float* __restrict__ Ap,
                            const __nv_bfloat16* __restrict__ Up,
                            const __nv_bfloat16* __restrict__ Gp,
                            const float* __restrict__ hin,
                            __nv_bfloat16* __restrict__ out1) {
    int cidx  = blockIdx.x * blockDim.x + threadIdx.x;
    int chunk = blockIdx.y;
    int b     = blockIdx.z;
    float h = hin[(b * NCH + chunk) * STATE + cidx];
    int t0 = chunk * TCH;
    for (int tl = 0; tl < TCH; tl++) {
        int t = t0 + tl;
        size_t row = (size_t)b * SEQ + t;
        float a  = (t == 0) ? 1.0f : Ap[(row - 1) * STATE + cidx];
        float up = __bfloat162float(Up[row * STATE + cidx]);
        h = a * h + up;
        float gg = __bfloat162float(Gp[row * STATE + cidx]);
        out1[row * STATE + cidx] = __float2bfloat16_rn(h * gg);
    }
}

// ---------------- Launch ----------------
extern "C" void kernel_launch(void* const* d_in, const int* in_sizes, int n_in,
                              void* d_out, int out_size) {
    const float* x    = (const float*)d_in[0];
    const float* ls   = (const float*)d_in[1];
    const float* rs   = (const float*)d_in[2];
    const float* ss   = (const float*)d_in[3];
    const float* Wk   = (const float*)d_in[4];
    const float* Wugg = (const float*)d_in[5];
    const float* Wout = (const float*)d_in[6];
    float* y = (float*)d_out;

    __nv_bfloat16 *p_xn, *p_WT, *p_WoutT, *p_out1, *p_U, *p_G;
    float *p_A, *p_chA, *p_chB, *p_hin;
    cudaGetSymbolAddress((void**)&p_xn,    g_xn);
    cudaGetSymbolAddress((void**)&p_WT,    g_WT);
    cudaGetSymbolAddress((void**)&p_WoutT, g_WoutT);
    cudaGetSymbolAddress((void**)&p_A,     g_A);
    cudaGetSymbolAddress((void**)&p_U,     g_U);
    cudaGetSymbolAddress((void**)&p_G,     g_G);
    cudaGetSymbolAddress((void**)&p_out1,  g_out1);
    cudaGetSymbolAddress((void**)&p_chA,   g_chA);
    cudaGetSymbolAddress((void**)&p_chB,   g_chB);
    cudaGetSymbolAddress((void**)&p_hin,   g_hin);

    cudaFuncSetAttribute(gemm_bf16, cudaFuncAttributeMaxDynamicSharedMemorySize, GEMM_SMEM);

    dim3 blk(32, 8);
    dim3 grd(2048/32, 1024/32);

    // launches 0..4: rmsnorm + 4x transpose_pack (GEMM1 deps)
    rmsnorm_kernel<<<ROWS, 256>>>(x, ls, rs, ss, p_xn);
    transpose_pack<<<grd, blk>>>(Wk,          2048, p_WT, 0);
    transpose_pack<<<grd, blk>>>(Wugg,        6144, p_WT, 1);
    transpose_pack<<<grd, blk>>>(Wugg + 2048, 6144, p_WT, 2);
    transpose_pack<<<grd, blk>>>(Wugg + 4096, 6144, p_WT, 3);

    // launch 5: GEMM1 (ncu -s 5 -c 1 lands here)
    gemm_bf16<<<dim3(NTOT/128, ROWS/128), 256, GEMM_SMEM>>>(
        p_xn, p_WT, NTOT, DIMS, DIMS/BK, 0, p_A, p_U, p_G, nullptr, nullptr);

    // Wout transpose only needed before GEMM2
    transpose_bf16<<<dim3(1024/32, 2048/32), blk>>>(Wout, p_WoutT, 2048, 1024);

    // Scan
    scan_phase1<<<dim3(STATE/256, NCH, BATCH), 256>>>(p_A, p_U, p_chA, p_chB);
    scan_phase2<<<(BATCH*STATE)/256, 256>>>(p_chA, p_chB, p_hin);
    scan_phase3<<<dim3(STATE/256, NCH, BATCH), 256>>>(p_A, p_U, p_G, p_hin, p_out1);

    // GEMM2: y = out1 @ Wout + x
    gemm_bf16<<<dim3(DIMS/128, ROWS/128), 256, GEMM_SMEM>>>(
        p_out1, p_WoutT, DIMS, STATE, STATE/BK, 1, nullptr, nullptr, nullptr, y, x);
}

// round 8
// speedup vs baseline: 1.2631x; 1.0383x over previous
#include <cuda_runtime.h>
#include <cuda_bf16.h>
#include <math.h>
#include <stdint.h>

// ---------------- Problem constants ----------------
#define BATCH   4
#define SEQ     2048
#define ROWS    (BATCH*SEQ)      // 8192
#define DIMS    1024
#define STATE   2048             // 2*DIMS
#define NTOT    (4*STATE)        // 8192 columns of GEMM1 output [K|u|gin|gout]
#define TCH     128              // scan chunk length
#define NCH     (SEQ/TCH)        // 16 chunks

// ---------------- Scratch (device globals; no allocation allowed) ----------------
__device__ __nv_bfloat16 g_xn[(size_t)ROWS*DIMS];       // 16MB  normalized input (bf16)
__device__ __nv_bfloat16 g_WT[(size_t)NTOT*DIMS];       // 16MB  [Wk|Wugg]^T as [n,k] bf16
__device__ __nv_bfloat16 g_WoutT[(size_t)DIMS*STATE];   // 4MB   Wout^T as [n,k] bf16
__device__ float g_C[(size_t)ROWS*NTOT];                // 256MB GEMM1 out (sig(K)|u|sig(gin)|sig(gout))
__device__ __nv_bfloat16 g_out1[(size_t)ROWS*STATE];    // 32MB  h*sigmoid(g_out) bf16
__device__ float g_chA[BATCH*NCH*STATE];
__device__ float g_chB[BATCH*NCH*STATE];
__device__ float g_hin[BATCH*NCH*STATE];

// ---------------- Helpers ----------------
__device__ __forceinline__ uint32_t smem_u32(const void* p) {
    uint32_t a;
    asm("{ .reg .u64 t; cvta.to.shared.u64 t, %1; cvt.u32.u64 %0, t; }" : "=r"(a) : "l"(p));
    return a;
}
__device__ __forceinline__ void cp16(uint32_t dst, const void* src) {
    asm volatile("cp.async.cg.shared.global [%0], [%1], 16;" :: "r"(dst), "l"(src) : "memory");
}
#define CP_COMMIT() asm volatile("cp.async.commit_group;" ::: "memory")

__device__ __forceinline__ void ldm_x4(uint32_t* r, uint32_t addr) {
    asm volatile("ldmatrix.sync.aligned.m8n8.x4.shared.b16 {%0,%1,%2,%3}, [%4];"
                 : "=r"(r[0]), "=r"(r[1]), "=r"(r[2]), "=r"(r[3]) : "r"(addr));
}
__device__ __forceinline__ void mma_bf16(float* c, const uint32_t* a,
                                         uint32_t b0, uint32_t b1) {
    asm volatile(
        "mma.sync.aligned.m16n8k16.row.col.f32.bf16.bf16.f32 "
        "{%0,%1,%2,%3},{%4,%5,%6,%7},{%8,%9},{%0,%1,%2,%3};"
        : "+f"(c[0]), "+f"(c[1]), "+f"(c[2]), "+f"(c[3])
        : "r"(a[0]), "r"(a[1]), "r"(a[2]), "r"(a[3]), "r"(b0), "r"(b1));
}
__device__ __forceinline__ float sigm(float v) { return 1.0f / (1.0f + expf(-v)); }

// ---------------- RMS split norm -> bf16 ----------------
__global__ void rmsnorm_kernel(const float* __restrict__ x,
                               const float* __restrict__ ls,
                               const float* __restrict__ rs,
                               const float* __restrict__ ss,
                               __nv_bfloat16* __restrict__ xn) {
    __shared__ float wsum[8];
    int row = blockIdx.x;
    int tid = threadIdx.x;                 // 256 threads, 4 elems each
    const float* xr = x + (size_t)row * DIMS;
    float4 xv = ((const float4*)xr)[tid];
    float s = xv.x*xv.x + xv.y*xv.y + xv.z*xv.z + xv.w*xv.w;
    #pragma unroll
    for (int o = 16; o; o >>= 1) s += __shfl_xor_sync(0xffffffffu, s, o);
    if ((tid & 31) == 0) wsum[tid >> 5] = s;
    __syncthreads();
    int half = tid >> 7;
    float tot = wsum[half*4+0] + wsum[half*4+1] + wsum[half*4+2] + wsum[half*4+3];
    float n = sqrtf(tot) * 0.04419417382415922f + 1e-8f;   // 1/sqrt(512)
    float inv = 1.0f / n;
    const float* sc = half ? rs : ls;
    int jb = (tid*4) & 511;
    float4 scv = ((const float4*)sc)[jb >> 2];
    float4 ssv = ((const float4*)ss)[tid];
    __nv_bfloat162 p0 = __floats2bfloat162_rn(xv.x * scv.x * inv * ssv.x,
                                              xv.y * scv.y * inv * ssv.y);
    __nv_bfloat162 p1 = __floats2bfloat162_rn(xv.z * scv.z * inv * ssv.z,
                                              xv.w * scv.w * inv * ssv.w);
    __nv_bfloat162* dst = (__nv_bfloat162*)(xn + (size_t)row * DIMS);
    dst[tid*2]   = p0;
    dst[tid*2+1] = p1;
}

// ---------------- Fused weight-prep: transpose Wk + Wugg into g_WT (one launch) ----------------
// z=0: Wk (LD 2048) -> WT rows [0,2048)
// z=1..3: Wugg cols [(z-1)*2048,(z)*2048) (LD 6144) -> WT rows [2048*z, 2048*z+2048)
__global__ void prep_WT(const float* __restrict__ Wk, const float* __restrict__ Wugg,
                        __nv_bfloat16* __restrict__ dst) {
    __shared__ float tile[32][33];
    int z = blockIdx.z;
    const float* src = (z == 0) ? Wk : (Wugg + (z - 1) * 2048);
    int srcLD = (z == 0) ? 2048 : 6144;
    size_t dstBase = (size_t)z * 2048 * 1024;
    int r0 = blockIdx.y * 32, c0 = blockIdx.x * 32;
    int tx = threadIdx.x, ty = threadIdx.y;   // 32 x 8
    #pragma unroll
    for (int i = 0; i < 32; i += 8)
        tile[ty+i][tx] = src[(size_t)(r0+ty+i)*srcLD + c0 + tx];
    __syncthreads();
    #pragma unroll
    for (int i = 0; i < 32; i += 8)
        dst[dstBase + (size_t)(c0+ty+i)*1024 + r0 + tx] = __float2bfloat16_rn(tile[tx][ty+i]);
}

// ---------------- Plain transpose fp32 -> bf16 (Wout) ----------------
__global__ void transpose_bf16(const float* __restrict__ src, __nv_bfloat16* __restrict__ dst,
                               int R, int C) {
    __shared__ float tile[32][33];
    int r0 = blockIdx.y * 32, c0 = blockIdx.x * 32;
    int tx = threadIdx.x, ty = threadIdx.y;   // 32 x 8
    #pragma unroll
    for (int i = 0; i < 32; i += 8)
        tile[ty+i][tx] = src[(size_t)(r0+ty+i)*C + c0 + tx];
    __syncthreads();
    #pragma unroll
    for (int i = 0; i < 32; i += 8)
        dst[(size_t)(c0+ty+i)*R + r0 + tx] = __float2bfloat16_rn(tile[tx][ty+i]);
}

// ---------------- Legacy-MMA bf16 GEMM (exact R3/631us version) ----------------
// CTA tile 128x128, BK=64, 3-stage cp.async pipeline, 256 threads (8 warps 2x4),
// warp tile 64x32, ldmatrix.x4 + m16n8k16 bf16 mma, 2 CTAs/SM.
// mode 0: GEMM1 epilogue (sigmoid on cols <2048 or >=4096)
// mode 1: add residual (resid[M,N])
#define BK 64
#define NST 3
#define AST (128*BK*2)         // 16384 bytes per A stage
#define BST (128*BK*2)         // 16384 bytes per B stage
#define GEMM_SMEM (NST*(AST+BST))   // 98304 = 96KB

__device__ __forceinline__ void fill_tiles(uint32_t aS, uint32_t bS,
        const __nv_bfloat16* __restrict__ A, const __nv_bfloat16* __restrict__ B,
        int m0, int n0, int K, int k0, int tid) {
    #pragma unroll
    for (int i = 0; i < 4; i++) {              // A: 128 rows x 8 16B-chunks
        int idx = tid + i*256;
        int r = idx >> 3, c = idx & 7;
        cp16(aS + r*128 + ((c ^ (r & 7)) << 4),
             A + (size_t)(m0 + r)*K + k0 + c*8);
    }
    #pragma unroll
    for (int i = 0; i < 4; i++) {              // B: 128 rows x 8 16B-chunks
        int idx = tid + i*256;
        int r = idx >> 3, c = idx & 7;
        cp16(bS + r*128 + ((c ^ (r & 7)) << 4),
             B + (size_t)(n0 + r)*K + k0 + c*8);
    }
    CP_COMMIT();
}

__global__ void __launch_bounds__(256, 2)
gemm_bf16(const __nv_bfloat16* __restrict__ A, const __nv_bfloat16* __restrict__ B,
          float* __restrict__ C, int N, int K, int NIT,
          int mode, const float* __restrict__ resid) {
    extern __shared__ char smraw[];
    const uint32_t sbase = smem_u32(smraw);

    const int tid  = threadIdx.x;
    const int wid  = tid >> 5;
    const int lane = tid & 31;
    const int m0 = blockIdx.y * 128;
    const int n0 = blockIdx.x * 128;
    const int wm0 = (wid >> 2) * 64;      // warp row origin (0/64)
    const int wn0 = (wid & 3) * 32;       // warp col origin (0/32/64/96)
    const int blk = lane >> 3;            // 0..3
    const int lr8 = lane & 7;
    const int kb2 = (blk >> 1) * 16;      // +16B for k8..15 half

    uint32_t offA[4], xrA[4], offB[2], xrB[2];
    #pragma unroll
    for (int mt = 0; mt < 4; mt++) {
        int r = wm0 + mt*16 + (blk & 1)*8 + lr8;
        offA[mt] = (uint32_t)r * 128u;
        xrA[mt]  = (uint32_t)(r & 7) << 4;
    }
    #pragma unroll
    for (int np = 0; np < 2; np++) {
        int r = wn0 + np*16 + (blk & 1)*8 + lr8;
        offB[np] = (uint32_t)r * 128u;
        xrB[np]  = (uint32_t)(r & 7) << 4;
    }

    float c[4][4][4];
    #pragma unroll
    for (int i = 0; i < 4; i++)
        #pragma unroll
        for (int j = 0; j < 4; j++)
            #pragma unroll
            for (int e = 0; e < 4; e++) c[i][j][e] = 0.0f;

    // Prologue: fill all 3 stages
    #pragma unroll
    for (int pf = 0; pf < NST; ++pf)
        fill_tiles(sbase + pf*(AST+BST), sbase + pf*(AST+BST) + AST,
                   A, B, m0, n0, K, pf*BK, tid);

    for (int it = 0; it < NIT; ++it) {
        const int s = it % NST;
        const uint32_t aS = sbase + s*(AST+BST);
        const uint32_t bS = aS + AST;

        int rem = NIT - 1 - it;
        if (rem >= 2)      asm volatile("cp.async.wait_group 2;" ::: "memory");
        else if (rem == 1) asm volatile("cp.async.wait_group 1;" ::: "memory");
        else               asm volatile("cp.async.wait_group 0;" ::: "memory");
        __syncthreads();

        #pragma unroll
        for (int kk = 0; kk < 4; ++kk) {
            uint32_t a[4][4], b[2][4];
            const uint32_t kbase = (uint32_t)(kk*32) + kb2;
            #pragma unroll
            for (int mt = 0; mt < 4; mt++)
                ldm_x4(a[mt], aS + offA[mt] + (kbase ^ xrA[mt]));
            #pragma unroll
            for (int np = 0; np < 2; np++)
                ldm_x4(b[np], bS + offB[np] + (kbase ^ xrB[np]));
            #pragma unroll
            for (int mt = 0; mt < 4; mt++)
                #pragma unroll
                for (int nt = 0; nt < 4; nt++) {
                    int np = nt >> 1, odd = nt & 1;
                    mma_bf16(c[mt][nt], a[mt], b[np][odd], b[np][2 + odd]);
                }
        }
        __syncthreads();   // everyone done reading stage s

        if (it + 3 < NIT)
            fill_tiles(aS, bS, A, B, m0, n0, K, (it + 3)*BK, tid);
    }

    // Epilogue: direct float2 stores
    const int g = lane >> 2, tig = lane & 3;
    #pragma unroll
    for (int mt = 0; mt < 4; mt++) {
        int row = m0 + wm0 + mt*16 + g;
        #pragma unroll
        for (int nt = 0; nt < 4; nt++) {
            int col = n0 + wn0 + nt*8 + 2*tig;
            float v0 = c[mt][nt][0], v1 = c[mt][nt][1];
            float v2 = c[mt][nt][2], v3 = c[mt][nt][3];
            if (mode == 0) {
                bool sg = (col < 2048) || (col >= 4096);
                if (sg) { v0 = sigm(v0); v1 = sigm(v1); v2 = sigm(v2); v3 = sigm(v3); }
            } else {
                v0 += resid[(size_t)row * N + col];
                v1 += resid[(size_t)row * N + col + 1];
                v2 += resid[(size_t)(row+8) * N + col];
                v3 += resid[(size_t)(row+8) * N + col + 1];
            }
            *(float2*)(C + (size_t)row * N + col)     = make_float2(v0, v1);
            *(float2*)(C + (size_t)(row+8) * N + col) = make_float2(v2, v3);
        }
    }
}

// ---------------- Chunked linear-recurrence scan (K carried in register) ----------------
__global__ void scan_phase1(const float* __restrict__ C,
                            float* __restrict__ chA, float* __restrict__ chB) {
    int cidx  = blockIdx.x * blockDim.x + threadIdx.x;   // 0..2047
    int chunk = blockIdx.y;
    int b     = blockIdx.z;
    size_t base = (size_t)b * SEQ * NTOT;
    float Aacc = 1.0f, Bacc = 0.0f;
    int t0 = chunk * TCH;
    float kprev = (t0 == 0) ? 1.0f : C[base + (size_t)(t0-1) * NTOT + cidx];
    for (int tl = 0; tl < TCH; tl++) {
        int t = t0 + tl;
        size_t r = base + (size_t)t * NTOT;
        float Kc = C[r + cidx];
        float u  = C[r + 2048 + cidx];
        float gi = C[r + 4096 + cidx];
        float a  = (t == 0) ? 1.0f : kprev;
        kprev = Kc;
        float up = u * gi * (1.0f - Kc);
        Aacc = a * Aacc;
        Bacc = a * Bacc + up;
    }
    int idx = (b * NCH + chunk) * STATE + cidx;
    chA[idx] = Aacc;
    chB[idx] = Bacc;
}

__global__ void scan_phase2(const float* __restrict__ chA,
                            const float* __restrict__ chB,
                            float* __restrict__ hin) {
    int i = blockIdx.x * blockDim.x + threadIdx.x;   // b*2048+c
    int b = i >> 11, cidx = i & 2047;
    float h = 0.0f;
    for (int ch = 0; ch < NCH; ch++) {
        int idx = (b * NCH + ch) * STATE + cidx;
        hin[idx] = h;
        h = chA[idx] * h + chB[idx];
    }
}

__global__ void scan_phase3(const float* __restrict__ C,
                            const float* __restrict__ hin,
                            __nv_bfloat16* __restrict__ out1) {
    int cidx  = blockIdx.x * blockDim.x + threadIdx.x;
    int chunk = blockIdx.y;
    int b     = blockIdx.z;
    size_t base = (size_t)b * SEQ * NTOT;
    float h = hin[(b * NCH + chunk) * STATE + cidx];
    int t0 = chunk * TCH;
    float kprev = (t0 == 0) ? 1.0f : C[base + (size_t)(t0-1) * NTOT + cidx];
    for (int tl = 0; tl < TCH; tl++) {
        int t = t0 + tl;
        size_t r = base + (size_t)t * NTOT;
        float Kc = C[r + cidx];
        float u  = C[r + 2048 + cidx];
        float gi = C[r + 4096 + cidx];
        float go = C[r + 6144 + cidx];
        float a  = (t == 0) ? 1.0f : kprev;
        kprev = Kc;
        float up = u * gi * (1.0f - Kc);
        h = a * h + up;
        out1[((size_t)b * SEQ + t) * STATE + cidx] = __float2bfloat16_rn(h * go);
    }
}

// ---------------- Launch ----------------
extern "C" void kernel_launch(void* const* d_in, const int* in_sizes, int n_in,
                              void* d_out, int out_size) {
    const float* x    = (const float*)d_in[0];
    const float* ls   = (const float*)d_in[1];
    const float* rs   = (const float*)d_in[2];
    const float* ss   = (const float*)d_in[3];
    const float* Wk   = (const float*)d_in[4];
    const float* Wugg = (const float*)d_in[5];
    const float* Wout = (const float*)d_in[6];
    float* y = (float*)d_out;

    __nv_bfloat16 *p_xn, *p_WT, *p_WoutT, *p_out1;
    float *p_C, *p_chA, *p_chB, *p_hin;
    cudaGetSymbolAddress((void**)&p_xn,    g_xn);
    cudaGetSymbolAddress((void**)&p_WT,    g_WT);
    cudaGetSymbolAddress((void**)&p_WoutT, g_WoutT);
    cudaGetSymbolAddress((void**)&p_C,     g_C);
    cudaGetSymbolAddress((void**)&p_out1,  g_out1);
    cudaGetSymbolAddress((void**)&p_chA,   g_chA);
    cudaGetSymbolAddress((void**)&p_chB,   g_chB);
    cudaGetSymbolAddress((void**)&p_hin,   g_hin);

    cudaFuncSetAttribute(gemm_bf16, cudaFuncAttributeMaxDynamicSharedMemorySize, GEMM_SMEM);

    dim3 blk(32, 8);

    // my launch 0 (global ~2): RMS split norm
    rmsnorm_kernel<<<ROWS, 256>>>(x, ls, rs, ss, p_xn);
    // my launch 1 (global ~3): fused Wk+Wugg transpose
    prep_WT<<<dim3(2048/32, 1024/32, 4), blk>>>(Wk, Wugg, p_WT);
    // my launch 2 (global ~4): Wout transpose
    transpose_bf16<<<dim3(1024/32, 2048/32), blk>>>(Wout, p_WoutT, 2048, 1024);
    // my launch 3 (global ~5, ncu -s 5 -c 1 target): GEMM1
    gemm_bf16<<<dim3(NTOT/128, ROWS/128), 256, GEMM_SMEM>>>(p_xn, p_WT, p_C,
                                                            NTOT, DIMS, DIMS/BK, 0, nullptr);

    // Scan
    scan_phase1<<<dim3(STATE/256, NCH, BATCH), 256>>>(p_C, p_chA, p_chB);
    scan_phase2<<<(BATCH*STATE)/256, 256>>>(p_chA, p_chB, p_hin);
    scan_phase3<<<dim3(STATE/256, NCH, BATCH), 256>>>(p_C, p_hin, p_out1);

    // GEMM2: y = out1 @ Wout + x
    gemm_bf16<<<dim3(DIMS/128, ROWS/128), 256, GEMM_SMEM>>>(p_out1, p_WoutT, y,
                                                            DIMS, STATE, STATE/BK, 1, x);
}

// round 9
// speedup vs baseline: 1.3385x; 1.0597x over previous
#include <cuda_runtime.h>
#include <cuda_bf16.h>
#include <math.h>
#include <stdint.h>

// ---------------- Problem constants ----------------
#define BATCH   4
#define SEQ     2048
#define ROWS    (BATCH*SEQ)      // 8192
#define DIMS    1024
#define STATE   2048             // 2*DIMS
#define NTOT    (4*STATE)        // 8192 columns of GEMM1 output [K|u|gin|gout]
#define TCH     128              // scan chunk length
#define NCH     (SEQ/TCH)        // 16 chunks

// ---------------- Scratch (device globals; no allocation allowed) ----------------
__device__ __nv_bfloat16 g_xn[(size_t)ROWS*DIMS];       // 16MB  normalized input (bf16)
__device__ __nv_bfloat16 g_WT[(size_t)NTOT*DIMS];       // 16MB  [Wk|Wugg]^T as [n,k] bf16
__device__ __nv_bfloat16 g_WoutT[(size_t)DIMS*STATE];   // 4MB   Wout^T as [n,k] bf16
__device__ float g_C[(size_t)ROWS*NTOT];                // 256MB GEMM1 out (sig(K)|u|sig(gin)|sig(gout))
__device__ __nv_bfloat16 g_out1[(size_t)ROWS*STATE];    // 32MB  h*sigmoid(g_out) bf16
__device__ float g_chA[BATCH*NCH*STATE];
__device__ float g_chB[BATCH*NCH*STATE];
__device__ float g_hin[BATCH*NCH*STATE];

// ---------------- Helpers ----------------
__device__ __forceinline__ uint32_t smem_u32(const void* p) {
    uint32_t a;
    asm("{ .reg .u64 t; cvta.to.shared.u64 t, %1; cvt.u32.u64 %0, t; }" : "=r"(a) : "l"(p));
    return a;
}
__device__ __forceinline__ void cp16(uint32_t dst, const void* src) {
    asm volatile("cp.async.cg.shared.global [%0], [%1], 16;" :: "r"(dst), "l"(src) : "memory");
}
#define CP_COMMIT() asm volatile("cp.async.commit_group;" ::: "memory")

__device__ __forceinline__ void ldm_x4(uint32_t* r, uint32_t addr) {
    asm volatile("ldmatrix.sync.aligned.m8n8.x4.shared.b16 {%0,%1,%2,%3}, [%4];"
                 : "=r"(r[0]), "=r"(r[1]), "=r"(r[2]), "=r"(r[3]) : "r"(addr));
}
__device__ __forceinline__ void mma_bf16(float* c, const uint32_t* a,
                                         uint32_t b0, uint32_t b1) {
    asm volatile(
        "mma.sync.aligned.m16n8k16.row.col.f32.bf16.bf16.f32 "
        "{%0,%1,%2,%3},{%4,%5,%6,%7},{%8,%9},{%0,%1,%2,%3};"
        : "+f"(c[0]), "+f"(c[1]), "+f"(c[2]), "+f"(c[3])
        : "r"(a[0]), "r"(a[1]), "r"(a[2]), "r"(a[3]), "r"(b0), "r"(b1));
}
// Fast sigmoid: MUFU.EX2-based exp + MUFU.RCP division (~4 SASS ops).
__device__ __forceinline__ float sigm(float v) {
    return __fdividef(1.0f, 1.0f + __expf(-v));
}

// ---------------- RMS split norm -> bf16 ----------------
__global__ void rmsnorm_kernel(const float* __restrict__ x,
                               const float* __restrict__ ls,
                               const float* __restrict__ rs,
                               const float* __restrict__ ss,
                               __nv_bfloat16* __restrict__ xn) {
    __shared__ float wsum[8];
    int row = blockIdx.x;
    int tid = threadIdx.x;                 // 256 threads, 4 elems each
    const float* xr = x + (size_t)row * DIMS;
    float4 xv = ((const float4*)xr)[tid];
    float s = xv.x*xv.x + xv.y*xv.y + xv.z*xv.z + xv.w*xv.w;
    #pragma unroll
    for (int o = 16; o; o >>= 1) s += __shfl_xor_sync(0xffffffffu, s, o);
    if ((tid & 31) == 0) wsum[tid >> 5] = s;
    __syncthreads();
    int half = tid >> 7;
    float tot = wsum[half*4+0] + wsum[half*4+1] + wsum[half*4+2] + wsum[half*4+3];
    float n = sqrtf(tot) * 0.04419417382415922f + 1e-8f;   // 1/sqrt(512)
    float inv = 1.0f / n;
    const float* sc = half ? rs : ls;
    int jb = (tid*4) & 511;
    float4 scv = ((const float4*)sc)[jb >> 2];
    float4 ssv = ((const float4*)ss)[tid];
    __nv_bfloat162 p0 = __floats2bfloat162_rn(xv.x * scv.x * inv * ssv.x,
                                              xv.y * scv.y * inv * ssv.y);
    __nv_bfloat162 p1 = __floats2bfloat162_rn(xv.z * scv.z * inv * ssv.z,
                                              xv.w * scv.w * inv * ssv.w);
    __nv_bfloat162* dst = (__nv_bfloat162*)(xn + (size_t)row * DIMS);
    dst[tid*2]   = p0;
    dst[tid*2+1] = p1;
}

// ---------------- Fused weight-prep: transpose Wk + Wugg into g_WT (one launch) ----------------
__global__ void prep_WT(const float* __restrict__ Wk, const float* __restrict__ Wugg,
                        __nv_bfloat16* __restrict__ dst) {
    __shared__ float tile[32][33];
    int z = blockIdx.z;
    const float* src = (z == 0) ? Wk : (Wugg + (z - 1) * 2048);
    int srcLD = (z == 0) ? 2048 : 6144;
    size_t dstBase = (size_t)z * 2048 * 1024;
    int r0 = blockIdx.y * 32, c0 = blockIdx.x * 32;
    int tx = threadIdx.x, ty = threadIdx.y;   // 32 x 8
    #pragma unroll
    for (int i = 0; i < 32; i += 8)
        tile[ty+i][tx] = src[(size_t)(r0+ty+i)*srcLD + c0 + tx];
    __syncthreads();
    #pragma unroll
    for (int i = 0; i < 32; i += 8)
        dst[dstBase + (size_t)(c0+ty+i)*1024 + r0 + tx] = __float2bfloat16_rn(tile[tx][ty+i]);
}

// ---------------- Plain transpose fp32 -> bf16 (Wout) ----------------
__global__ void transpose_bf16(const float* __restrict__ src, __nv_bfloat16* __restrict__ dst,
                               int R, int C) {
    __shared__ float tile[32][33];
    int r0 = blockIdx.y * 32, c0 = blockIdx.x * 32;
    int tx = threadIdx.x, ty = threadIdx.y;   // 32 x 8
    #pragma unroll
    for (int i = 0; i < 32; i += 8)
        tile[ty+i][tx] = src[(size_t)(r0+ty+i)*C + c0 + tx];
    __syncthreads();
    #pragma unroll
    for (int i = 0; i < 32; i += 8)
        dst[(size_t)(c0+ty+i)*R + r0 + tx] = __float2bfloat16_rn(tile[tx][ty+i]);
}

// ---------------- Legacy-MMA bf16 GEMM (R3 mainloop + hoisted fill addresses) ----------------
// CTA tile 128x128, BK=64, 3-stage cp.async pipeline, 256 threads (8 warps 2x4),
// warp tile 64x32, ldmatrix.x4 + m16n8k16 bf16 mma, 2 CTAs/SM.
#define BK 64
#define NST 3
#define AST (128*BK*2)         // 16384 bytes per A stage
#define BST (128*BK*2)         // 16384 bytes per B stage
#define GEMM_SMEM (NST*(AST+BST))   // 98304 = 96KB

__global__ void __launch_bounds__(256, 2)
gemm_bf16(const __nv_bfloat16* __restrict__ A, const __nv_bfloat16* __restrict__ B,
          float* __restrict__ C, int N, int K, int NIT,
          int mode, const float* __restrict__ resid) {
    extern __shared__ char smraw[];
    const uint32_t sbase = smem_u32(smraw);

    const int tid  = threadIdx.x;
    const int wid  = tid >> 5;
    const int lane = tid & 31;
    const int m0 = blockIdx.y * 128;
    const int n0 = blockIdx.x * 128;
    const int wm0 = (wid >> 2) * 64;      // warp row origin (0/64)
    const int wn0 = (wid & 3) * 32;       // warp col origin (0/32/64/96)
    const int blk = lane >> 3;            // 0..3
    const int lr8 = lane & 7;
    const int kb2 = (blk >> 1) * 16;      // +16B for k8..15 half

    // Hoisted fill addressing: per-thread smem swizzled offsets + global offsets
    uint32_t sOff[4];
    const __nv_bfloat16 *gA[4], *gB[4];
    {
        int r = tid >> 3, c = tid & 7;
        #pragma unroll
        for (int i = 0; i < 4; i++) {
            int rr = r + i * 32;
            sOff[i] = (uint32_t)(rr * 128 + ((c ^ (rr & 7)) << 4));
            gA[i] = A + (size_t)(m0 + rr) * K + c * 8;
            gB[i] = B + (size_t)(n0 + rr) * K + c * 8;
        }
    }

    uint32_t offA[4], xrA[4], offB[2], xrB[2];
    #pragma unroll
    for (int mt = 0; mt < 4; mt++) {
        int r = wm0 + mt*16 + (blk & 1)*8 + lr8;
        offA[mt] = (uint32_t)r * 128u;
        xrA[mt]  = (uint32_t)(r & 7) << 4;
    }
    #pragma unroll
    for (int np = 0; np < 2; np++) {
        int r = wn0 + np*16 + (blk & 1)*8 + lr8;
        offB[np] = (uint32_t)r * 128u;
        xrB[np]  = (uint32_t)(r & 7) << 4;
    }

    float c[4][4][4];
    #pragma unroll
    for (int i = 0; i < 4; i++)
        #pragma unroll
        for (int j = 0; j < 4; j++)
            #pragma unroll
            for (int e = 0; e < 4; e++) c[i][j][e] = 0.0f;

    // Prologue: fill all 3 stages
    #pragma unroll
    for (int pf = 0; pf < NST; ++pf) {
        const uint32_t aS = sbase + pf*(AST+BST);
        const uint32_t bS = aS + AST;
        const int k0 = pf * BK;
        #pragma unroll
        for (int i = 0; i < 4; i++) cp16(aS + sOff[i], gA[i] + k0);
        #pragma unroll
        for (int i = 0; i < 4; i++) cp16(bS + sOff[i], gB[i] + k0);
        CP_COMMIT();
    }

    for (int it = 0; it < NIT; ++it) {
        const int s = it % NST;
        const uint32_t aS = sbase + s*(AST+BST);
        const uint32_t bS = aS + AST;

        int rem = NIT - 1 - it;
        if (rem >= 2)      asm volatile("cp.async.wait_group 2;" ::: "memory");
        else if (rem == 1) asm volatile("cp.async.wait_group 1;" ::: "memory");
        else               asm volatile("cp.async.wait_group 0;" ::: "memory");
        __syncthreads();

        #pragma unroll
        for (int kk = 0; kk < 4; ++kk) {
            uint32_t a[4][4], b[2][4];
            const uint32_t kbase = (uint32_t)(kk*32) + kb2;
            #pragma unroll
            for (int mt = 0; mt < 4; mt++)
                ldm_x4(a[mt], aS + offA[mt] + (kbase ^ xrA[mt]));
            #pragma unroll
            for (int np = 0; np < 2; np++)
                ldm_x4(b[np], bS + offB[np] + (kbase ^ xrB[np]));
            #pragma unroll
            for (int mt = 0; mt < 4; mt++)
                #pragma unroll
                for (int nt = 0; nt < 4; nt++) {
                    int np = nt >> 1, odd = nt & 1;
                    mma_bf16(c[mt][nt], a[mt], b[np][odd], b[np][2 + odd]);
                }
        }
        __syncthreads();   // everyone done reading stage s

        if (it + 3 < NIT) {
            const int k0 = (it + 3) * BK;
            #pragma unroll
            for (int i = 0; i < 4; i++) cp16(aS + sOff[i], gA[i] + k0);
            #pragma unroll
            for (int i = 0; i < 4; i++) cp16(bS + sOff[i], gB[i] + k0);
            CP_COMMIT();
        }
    }

    // Epilogue: direct float2 stores
    const int g = lane >> 2, tig = lane & 3;
    #pragma unroll
    for (int mt = 0; mt < 4; mt++) {
        int row = m0 + wm0 + mt*16 + g;
        #pragma unroll
        for (int nt = 0; nt < 4; nt++) {
            int col = n0 + wn0 + nt*8 + 2*tig;
            float v0 = c[mt][nt][0], v1 = c[mt][nt][1];
            float v2 = c[mt][nt][2], v3 = c[mt][nt][3];
            if (mode == 0) {
                bool sg = (col < 2048) || (col >= 4096);
                if (sg) { v0 = sigm(v0); v1 = sigm(v1); v2 = sigm(v2); v3 = sigm(v3); }
            } else {
                v0 += resid[(size_t)row * N + col];
                v1 += resid[(size_t)row * N + col + 1];
                v2 += resid[(size_t)(row+8) * N + col];
                v3 += resid[(size_t)(row+8) * N + col + 1];
            }
            *(float2*)(C + (size_t)row * N + col)     = make_float2(v0, v1);
            *(float2*)(C + (size_t)(row+8) * N + col) = make_float2(v2, v3);
        }
    }
}

// ---------------- Chunked linear-recurrence scan (K carried in register) ----------------
__global__ void scan_phase1(const float* __restrict__ C,
                            float* __restrict__ chA, float* __restrict__ chB) {
    int cidx  = blockIdx.x * blockDim.x + threadIdx.x;   // 0..2047
    int chunk = blockIdx.y;
    int b     = blockIdx.z;
    size_t base = (size_t)b * SEQ * NTOT;
    float Aacc = 1.0f, Bacc = 0.0f;
    int t0 = chunk * TCH;
    float kprev = (t0 == 0) ? 1.0f : C[base + (size_t)(t0-1) * NTOT + cidx];
    for (int tl = 0; tl < TCH; tl++) {
        int t = t0 + tl;
        size_t r = base + (size_t)t * NTOT;
        float Kc = C[r + cidx];
        float u  = C[r + 2048 + cidx];
        float gi = C[r + 4096 + cidx];
        float a  = (t == 0) ? 1.0f : kprev;
        kprev = Kc;
        float up = u * gi * (1.0f - Kc);
        Aacc = a * Aacc;
        Bacc = a * Bacc + up;
    }
    int idx = (b * NCH + chunk) * STATE + cidx;
    chA[idx] = Aacc;
    chB[idx] = Bacc;
}

__global__ void scan_phase2(const float* __restrict__ chA,
                            const float* __restrict__ chB,
                            float* __restrict__ hin) {
    int i = blockIdx.x * blockDim.x + threadIdx.x;   // b*2048+c
    int b = i >> 11, cidx = i & 2047;
    float h = 0.0f;
    for (int ch = 0; ch < NCH; ch++) {
        int idx = (b * NCH + ch) * STATE + cidx;
        hin[idx] = h;
        h = chA[idx] * h + chB[idx];
    }
}

__global__ void scan_phase3(const float* __restrict__ C,
                            const float* __restrict__ hin,
                            __nv_bfloat16* __restrict__ out1) {
    int cidx  = blockIdx.x * blockDim.x + threadIdx.x;
    int chunk = blockIdx.y;
    int b     = blockIdx.z;
    size_t base = (size_t)b * SEQ * NTOT;
    float h = hin[(b * NCH + chunk) * STATE + cidx];
    int t0 = chunk * TCH;
    float kprev = (t0 == 0) ? 1.0f : C[base + (size_t)(t0-1) * NTOT + cidx];
    for (int tl = 0; tl < TCH; tl++) {
        int t = t0 + tl;
        size_t r = base + (size_t)t * NTOT;
        float Kc = C[r + cidx];
        float u  = C[r + 2048 + cidx];
        float gi = C[r + 4096 + cidx];
        float go = C[r + 6144 + cidx];
        float a  = (t == 0) ? 1.0f : kprev;
        kprev = Kc;
        float up = u * gi * (1.0f - Kc);
        h = a * h + up;
        out1[((size_t)b * SEQ + t) * STATE + cidx] = __float2bfloat16_rn(h * go);
    }
}

// ---------------- Launch ----------------
extern "C" void kernel_launch(void* const* d_in, const int* in_sizes, int n_in,
                              void* d_out, int out_size) {
    const float* x    = (const float*)d_in[0];
    const float* ls   = (const float*)d_in[1];
    const float* rs   = (const float*)d_in[2];
    const float* ss   = (const float*)d_in[3];
    const float* Wk   = (const float*)d_in[4];
    const float* Wugg = (const float*)d_in[5];
    const float* Wout = (const float*)d_in[6];
    float* y = (float*)d_out;

    __nv_bfloat16 *p_xn, *p_WT, *p_WoutT, *p_out1;
    float *p_C, *p_chA, *p_chB, *p_hin;
    cudaGetSymbolAddress((void**)&p_xn,    g_xn);
    cudaGetSymbolAddress((void**)&p_WT,    g_WT);
    cudaGetSymbolAddress((void**)&p_WoutT, g_WoutT);
    cudaGetSymbolAddress((void**)&p_C,     g_C);
    cudaGetSymbolAddress((void**)&p_out1,  g_out1);
    cudaGetSymbolAddress((void**)&p_chA,   g_chA);
    cudaGetSymbolAddress((void**)&p_chB,   g_chB);
    cudaGetSymbolAddress((void**)&p_hin,   g_hin);

    cudaFuncSetAttribute(gemm_bf16, cudaFuncAttributeMaxDynamicSharedMemorySize, GEMM_SMEM);

    dim3 blk(32, 8);

    rmsnorm_kernel<<<ROWS, 256>>>(x, ls, rs, ss, p_xn);
    prep_WT<<<dim3(2048/32, 1024/32, 4), blk>>>(Wk, Wugg, p_WT);
    transpose_bf16<<<dim3(1024/32, 2048/32), blk>>>(Wout, p_WoutT, 2048, 1024);
    // global launch index 5 -> ncu profiles GEMM1
    gemm_bf16<<<dim3(NTOT/128, ROWS/128), 256, GEMM_SMEM>>>(p_xn, p_WT, p_C,
                                                            NTOT, DIMS, DIMS/BK, 0, nullptr);

    scan_phase1<<<dim3(STATE/256, NCH, BATCH), 256>>>(p_C, p_chA, p_chB);
    scan_phase2<<<(BATCH*STATE)/256, 256>>>(p_chA, p_chB, p_hin);
    scan_phase3<<<dim3(STATE/256, NCH, BATCH), 256>>>(p_C, p_hin, p_out1);

    gemm_bf16<<<dim3(DIMS/128, ROWS/128), 256, GEMM_SMEM>>>(p_out1, p_WoutT, y,
                                                            DIMS, STATE, STATE/BK, 1, x);
}